// round 8
// baseline (speedup 1.0000x reference)
#include <cuda_runtime.h>
#include <math.h>

#define NB     2048
#define KOBJ   8
#define H1     250
#define ROWS   (NB*KOBJ)       // 16384

__device__ float g_s1 [ROWS*H1];
__device__ float g_P  [ROWS*H1];
__device__ float g_Q  [ROWS*H1];
__device__ float g_eff[ROWS*H1];

typedef unsigned long long u64;

__device__ __forceinline__ float warp_sum(float v) {
#pragma unroll
    for (int o = 16; o; o >>= 1) v += __shfl_xor_sync(0xffffffffu, v, o);
    return v;
}
__device__ __forceinline__ void ffma2(u64& d, u64 a, u64 b) {
    asm("fma.rn.f32x2 %0, %1, %2, %0;" : "+l"(d) : "l"(a), "l"(b));
}
__device__ __forceinline__ u64 dup2(float x) {
    u64 r;
    asm("mov.b64 %0, {%1, %1};" : "=l"(r) : "r"(__float_as_uint(x)));
    return r;
}
__device__ __forceinline__ float2 unpk(u64 v) {
    float2 f;
    asm("mov.b64 {%0, %1}, %2;" : "=f"(f.x), "=f"(f.y) : "l"(v));
    return f;
}
__device__ __forceinline__ float fsel(float4 v, int m) {
    return (m == 0) ? v.x : (m == 1) ? v.y : (m == 2) ? v.z : v.w;
}
__device__ __forceinline__ void cp8(void* s, const void* g) {
    asm volatile("cp.async.ca.shared.global [%0], [%1], 8;"
                 :: "r"((unsigned)__cvta_generic_to_shared(s)), "l"(g));
}
__device__ __forceinline__ void cp4(void* s, const void* g) {
    asm volatile("cp.async.ca.shared.global [%0], [%1], 4;"
                 :: "r"((unsigned)__cvta_generic_to_shared(s)), "l"(g));
}
#define CP_COMMIT() asm volatile("cp.async.commit_group;")
#define CP_WAIT1()  asm volatile("cp.async.wait_group 1;")

__device__ __forceinline__ int colmap(int tx, int cc) {
    return (cc < 4) ? (tx * 4 + cc) : (128 + tx * 4 + (cc - 4));
}

// ---------------------------------------------------------------------------
// Tiled SGEMM (R5/R7-best): BM=64, BN=256(>=N), BK=16; 256 threads;
// cp.async double-buffered A+W tiles; dup2 in loop; FFMA2 accumulators.
// ---------------------------------------------------------------------------
template <int EPI>
__global__ __launch_bounds__(256, 2)
void gemm_kernel(const float* __restrict__ A, const float* __restrict__ W,
                 const float* __restrict__ bias, const float* __restrict__ g,
                 const float* __restrict__ bt, float* __restrict__ C,
                 int M, int K, int N)
{
    __shared__ float sA[2][64 * 20];
    __shared__ float sW[2][16 * 256];
    const int tid = threadIdx.x;
    const int tx = tid & 31, ty = tid >> 5;
    const int row0 = blockIdx.x * 64;
    const int NT = (K + 15) >> 4;

    auto issue = [&](int t, int buf) {
        int kt = t * 16;
#pragma unroll
        for (int c = 0; c < 2; ++c) {
            int q = tid + c * 256;
            int r = q >> 3, kk0 = (q & 7) * 2;
            int k = kt + kk0;
            float* d = &sA[buf][r * 20 + kk0];
            if (k + 2 <= K)     cp8(d, &A[(size_t)(row0 + r) * K + k]);
            else if (k < K) { cp4(d, &A[(size_t)(row0 + r) * K + k]); d[1] = 0.f; }
            else *(float2*)d = make_float2(0.f, 0.f);
        }
#pragma unroll
        for (int c = 0; c < 8; ++c) {
            int q = tid + c * 256;
            int kk = q >> 7, n0 = (q & 127) * 2;
            int k = kt + kk;
            float* d = &sW[buf][kk * 256 + n0];
            if (k < K && n0 + 2 <= N)   cp8(d, &W[(size_t)k * N + n0]);
            else if (k < K && n0 < N) { cp4(d, &W[(size_t)k * N + n0]); d[1] = 0.f; }
            else *(float2*)d = make_float2(0.f, 0.f);
        }
    };

    u64 acc2[8][4];
#pragma unroll
    for (int r = 0; r < 8; ++r)
#pragma unroll
        for (int p = 0; p < 4; ++p) acc2[r][p] = 0ull;

    issue(0, 0); CP_COMMIT();
    for (int t = 0; t < NT; ++t) {
        if (t + 1 < NT) issue(t + 1, (t + 1) & 1);
        CP_COMMIT();
        CP_WAIT1();
        __syncthreads();
        const float* aT = sA[t & 1];
        const float* wT = sW[t & 1];
#pragma unroll
        for (int k4 = 0; k4 < 4; ++k4) {
            float4 a4[8];
#pragma unroll
            for (int rr = 0; rr < 8; ++rr)
                a4[rr] = *(const float4*)&aT[(ty * 8 + rr) * 20 + k4 * 4];
#pragma unroll
            for (int m = 0; m < 4; ++m) {
                int kk = k4 * 4 + m;
                ulonglong2 wv0 = *(const ulonglong2*)&wT[kk * 256 + tx * 4];
                ulonglong2 wv1 = *(const ulonglong2*)&wT[kk * 256 + 128 + tx * 4];
                u64 w2[4] = {wv0.x, wv0.y, wv1.x, wv1.y};
#pragma unroll
                for (int rr = 0; rr < 8; ++rr) {
                    u64 ad = dup2(fsel(a4[rr], m));
#pragma unroll
                    for (int p = 0; p < 4; ++p) ffma2(acc2[rr][p], ad, w2[p]);
                }
            }
        }
        __syncthreads();
    }

    if (EPI == 0) {
#pragma unroll
        for (int rr = 0; rr < 8; ++rr) {
            int row = row0 + ty * 8 + rr;
#pragma unroll
            for (int p = 0; p < 4; ++p) {
                float2 f = unpk(acc2[rr][p]);
                int n0 = colmap(tx, 2 * p);
                if (n0 < N)     C[(size_t)row * N + n0]     = f.x;
                if (n0 + 1 < N) C[(size_t)row * N + n0 + 1] = f.y;
            }
        }
    } else {
        float invN = 1.f / (float)N;
#pragma unroll
        for (int rr = 0; rr < 8; ++rr) {
            int row = row0 + ty * 8 + rr;
            float v[8]; float s = 0.f;
#pragma unroll
            for (int cc = 0; cc < 8; ++cc) {
                float2 f = unpk(acc2[rr][cc >> 1]);
                float raw = (cc & 1) ? f.y : f.x;
                int n = colmap(tx, cc);
                float t = 0.f;
                if (n < N) t = fmaxf(raw + bias[n], 0.f);
                v[cc] = t; s += t;
            }
            s = warp_sum(s);
            float mu = s * invN;
            float q = 0.f;
#pragma unroll
            for (int cc = 0; cc < 8; ++cc) {
                int n = colmap(tx, cc);
                if (n < N) { float d = v[cc] - mu; q += d * d; }
            }
            q = warp_sum(q);
            float rs = rsqrtf(q * invN + 1e-5f);
#pragma unroll
            for (int cc = 0; cc < 8; ++cc) {
                int n = colmap(tx, cc);
                if (n < N) C[(size_t)row * N + n] = (v[cc] - mu) * rs * g[n] + bt[n];
            }
        }
    }
}

// ---------------------------------------------------------------------------
// Output GEMM (R5/R7-best): [s1|effect|x] @ out_W + out_b. K=1076, N=250.
// ---------------------------------------------------------------------------
__global__ __launch_bounds__(256, 2)
void out_gemm_kernel(const float* __restrict__ s1, const float* __restrict__ eff,
                     const float* __restrict__ x, const float* __restrict__ W,
                     const float* __restrict__ bias, float* __restrict__ C)
{
    const int K = 1076, N = 250;
    __shared__ float sA[2][64 * 20];
    __shared__ float sW[2][16 * 256];
    const int tid = threadIdx.x;
    const int tx = tid & 31, ty = tid >> 5;
    const int row0 = blockIdx.x * 64;
    const int NT = (K + 15) >> 4;   // 68

    auto issue = [&](int t, int buf) {
        int kt = t * 16;
#pragma unroll
        for (int c = 0; c < 4; ++c) {
            int q = tid + c * 256;
            int r = q >> 4, kk = q & 15;
            int k = kt + kk;
            int row = row0 + r;
            float* d = &sA[buf][r * 20 + kk];
            if (k < 250)       cp4(d, &s1 [(size_t)row * 250 + k]);
            else if (k < 500)  cp4(d, &eff[(size_t)row * 250 + (k - 250)]);
            else if (k < 1076) cp4(d, &x  [(size_t)row * 576 + (k - 500)]);
            else *d = 0.f;
        }
#pragma unroll
        for (int c = 0; c < 8; ++c) {
            int q = tid + c * 256;
            int kk = q >> 7, n0 = (q & 127) * 2;
            int k = kt + kk;
            float* d = &sW[buf][kk * 256 + n0];
            if (k < K && n0 + 2 <= N)   cp8(d, &W[(size_t)k * N + n0]);
            else if (k < K && n0 < N) { cp4(d, &W[(size_t)k * N + n0]); d[1] = 0.f; }
            else *(float2*)d = make_float2(0.f, 0.f);
        }
    };

    u64 acc2[8][4];
#pragma unroll
    for (int r = 0; r < 8; ++r)
#pragma unroll
        for (int p = 0; p < 4; ++p) acc2[r][p] = 0ull;

    issue(0, 0); CP_COMMIT();
    for (int t = 0; t < NT; ++t) {
        if (t + 1 < NT) issue(t + 1, (t + 1) & 1);
        CP_COMMIT();
        CP_WAIT1();
        __syncthreads();
        const float* aT = sA[t & 1];
        const float* wT = sW[t & 1];
#pragma unroll
        for (int k4 = 0; k4 < 4; ++k4) {
            float4 a4[8];
#pragma unroll
            for (int rr = 0; rr < 8; ++rr)
                a4[rr] = *(const float4*)&aT[(ty * 8 + rr) * 20 + k4 * 4];
#pragma unroll
            for (int m = 0; m < 4; ++m) {
                int kk = k4 * 4 + m;
                ulonglong2 wv0 = *(const ulonglong2*)&wT[kk * 256 + tx * 4];
                ulonglong2 wv1 = *(const ulonglong2*)&wT[kk * 256 + 128 + tx * 4];
                u64 w2[4] = {wv0.x, wv0.y, wv1.x, wv1.y};
#pragma unroll
                for (int rr = 0; rr < 8; ++rr) {
                    u64 ad = dup2(fsel(a4[rr], m));
#pragma unroll
                    for (int p = 0; p < 4; ++p) ffma2(acc2[rr][p], ad, w2[p]);
                }
            }
        }
        __syncthreads();
    }
#pragma unroll
    for (int rr = 0; rr < 8; ++rr) {
        int row = row0 + ty * 8 + rr;
#pragma unroll
        for (int p = 0; p < 4; ++p) {
            float2 f = unpk(acc2[rr][p]);
            int n0 = colmap(tx, 2 * p);
            if (n0 < N)     C[(size_t)row * N + n0]     = f.x + bias[n0];
            if (n0 + 1 < N) C[(size_t)row * N + n0 + 1] = f.y + bias[n0 + 1];
        }
    }
}

// ---------------------------------------------------------------------------
// Fused pair kernel v3: MERGED att+ctx GEMM loop (att result only needed in
// ctx epilogue). One block per b (56 rows), 256 threads, BK=32, 8 phases.
// Per kk per warp: 42 FFMA2 : 3 W-LDS.128 : 3.5 A-LDS.64 (broadcast).
// SMEM: sC 56x256 | union{ staging 4032 , ctx tile 32x256 + att tile 32x128 }
//       | sAtt   = 26688 floats = 106752 B (2 blocks/SM).
// ---------------------------------------------------------------------------
#define SC_STRIDE 256
#define SM_SC   0
#define SM_UN   (56 * SC_STRIDE)        /* 14336 */
#define SM_WA   (SM_UN + 8192)          /* att tile after ctx tile */
#define SM_ATT  (SM_UN + 12288)         /* 26624 */
#define SM_TOT  (SM_ATT + 64)           /* 26688 floats */

__global__ __launch_bounds__(256, 2)
void pair_kernel(const float* __restrict__ P, const float* __restrict__ Q,
                 const float* __restrict__ core_b, const float* __restrict__ core_g,
                 const float* __restrict__ core_bt,
                 const float* __restrict__ ctxW, const float* __restrict__ ctx_b,
                 const float* __restrict__ ctx_g, const float* __restrict__ ctx_bt,
                 const float* __restrict__ attW1, const float* __restrict__ att_b1,
                 const float* __restrict__ att_g, const float* __restrict__ att_bt,
                 const float* __restrict__ attW2, const float* __restrict__ att_b2,
                 float* __restrict__ effect)
{
    extern __shared__ float sm[];
    float* sC   = sm + SM_SC;
    float* sP   = sm + SM_UN;            // staging (phase 1 only)
    float* sQ   = sm + SM_UN + 2016;
    float* sW   = sm + SM_UN;            // ctx tile 32x256 (phases 2+)
    float* sWA  = sm + SM_WA;            // att tile 32x128
    float* sAtt = sm + SM_ATT;

    const int tid = threadIdx.x;
    const int tx = tid & 31, ty = tid >> 5;
    const int b = blockIdx.x;

    // --- phase 1: load P,Q rows, build core_out into sC ---
    for (int idx = tid; idx < 8 * 250; idx += 256) {
        int i = idx / 250, c = idx % 250;
        sP[i * 252 + c] = P[(size_t)(b * 8 + i) * 250 + c];
        sQ[i * 252 + c] = Q[(size_t)(b * 8 + i) * 250 + c];
    }
    __syncthreads();

    for (int r = ty; r < 56; r += 8) {
        int i = r / 7, jj = r % 7;
        int j = jj + (jj >= i ? 1 : 0);
        float v[8]; float s = 0.f;
#pragma unroll
        for (int t = 0; t < 8; ++t) {
            int c = tx + 32 * t;
            float val = 0.f;
            if (c < 250) val = fmaxf(sP[i * 252 + c] + sQ[j * 252 + c] + core_b[c], 0.f);
            v[t] = val; s += val;
        }
        s = warp_sum(s);
        float mu = s * (1.f / 250.f);
        float q = 0.f;
#pragma unroll
        for (int t = 0; t < 8; ++t) {
            int c = tx + 32 * t;
            if (c < 250) { float d = v[t] - mu; q += d * d; }
        }
        q = warp_sum(q);
        float rs = rsqrtf(q * (1.f / 250.f) + 1e-5f);
#pragma unroll
        for (int t = 0; t < 8; ++t) {
            int c = tx + 32 * t;
            if (c < 250) sC[r * SC_STRIDE + c] = (v[t] - mu) * rs * core_g[c] + core_bt[c];
            else         sC[r * SC_STRIDE + c] = 0.f;
        }
    }
    __syncthreads();   // staging dead; W tiles may overwrite

    // --- phase 2: MERGED att+ctx GEMM over K=250, BK=32 (8 phases) ---
    u64 accA2[7][2];
    u64 accC2[7][4];
#pragma unroll
    for (int r = 0; r < 7; ++r) {
        accA2[r][0] = accA2[r][1] = 0ull;
#pragma unroll
        for (int p = 0; p < 4; ++p) accC2[r][p] = 0ull;
    }

    for (int t8 = 0; t8 < 8; ++t8) {
        int kt0 = t8 * 32;
        // ctx tile 32x256 via float2 (16 per thread)
#pragma unroll
        for (int c = 0; c < 16; ++c) {
            int q = tid + c * 256;
            int kk = q >> 7, n2 = q & 127;
            int k = kt0 + kk, n = n2 * 2;
            float2* d = (float2*)&sW[kk * 256 + n];
            *d = (k < 250 && n + 2 <= 250)
                 ? *(const float2*)&ctxW[(size_t)k * 250 + n]
                 : make_float2(0.f, 0.f);
        }
        // att tile 32x128 via float2 (8 per thread)
#pragma unroll
        for (int c = 0; c < 8; ++c) {
            int q = tid + c * 256;
            int kk = q >> 6, n2 = q & 63;
            int k = kt0 + kk, n = n2 * 2;
            float2* d = (float2*)&sWA[kk * 128 + n];
            *d = (k < 250 && n + 2 <= 100)
                 ? *(const float2*)&attW1[(size_t)k * 100 + n]
                 : make_float2(0.f, 0.f);
        }
        __syncthreads();
#pragma unroll
        for (int k2 = 0; k2 < 16; ++k2) {
            int kt = kt0 + k2 * 2;
            float2 a2[7];
#pragma unroll
            for (int rr = 0; rr < 7; ++rr)
                a2[rr] = *(const float2*)&sC[(ty * 7 + rr) * SC_STRIDE + kt];
#pragma unroll
            for (int m = 0; m < 2; ++m) {
                int kk = k2 * 2 + m;
                ulonglong2 wv0 = *(const ulonglong2*)&sW[kk * 256 + tx * 4];
                ulonglong2 wv1 = *(const ulonglong2*)&sW[kk * 256 + 128 + tx * 4];
                ulonglong2 wa  = *(const ulonglong2*)&sWA[kk * 128 + tx * 4];
#pragma unroll
                for (int rr = 0; rr < 7; ++rr) {
                    u64 ad = dup2(m ? a2[rr].y : a2[rr].x);
                    ffma2(accC2[rr][0], ad, wv0.x);
                    ffma2(accC2[rr][1], ad, wv0.y);
                    ffma2(accC2[rr][2], ad, wv1.x);
                    ffma2(accC2[rr][3], ad, wv1.y);
                    ffma2(accA2[rr][0], ad, wa.x);
                    ffma2(accA2[rr][1], ad, wa.y);
                }
            }
        }
        __syncthreads();
    }

    // --- attention epilogue: tanh, LN(100), dot attW2, sigmoid ---
#pragma unroll
    for (int rr = 0; rr < 7; ++rr) {
        int row = ty * 7 + rr;
        float h[4]; float s = 0.f;
#pragma unroll
        for (int cc = 0; cc < 4; ++cc) {
            float2 f = unpk(accA2[rr][cc >> 1]);
            float raw = (cc & 1) ? f.y : f.x;
            int c = tx * 4 + cc;
            float t = 0.f;
            if (c < 100) t = tanhf(raw + att_b1[c]);
            h[cc] = t; s += t;
        }
        s = warp_sum(s);
        float mu = s * (1.f / 100.f);
        float q = 0.f;
#pragma unroll
        for (int cc = 0; cc < 4; ++cc) {
            int c = tx * 4 + cc;
            if (c < 100) { float d = h[cc] - mu; q += d * d; }
        }
        q = warp_sum(q);
        float rs = rsqrtf(q * (1.f / 100.f) + 1e-5f);
        float p = 0.f;
#pragma unroll
        for (int cc = 0; cc < 4; ++cc) {
            int c = tx * 4 + cc;
            if (c < 100) p += ((h[cc] - mu) * rs * att_g[c] + att_bt[c]) * attW2[c];
        }
        p = warp_sum(p);
        if (tx == 0) sAtt[row] = 1.f / (1.f + expf(-(p + att_b2[0])));
    }
    __syncthreads();

    // --- ctx epilogue + effect reduce (warp ty owns i-group ty) ---
    float eff[8];
#pragma unroll
    for (int cc = 0; cc < 8; ++cc) eff[cc] = 0.f;
#pragma unroll
    for (int rr = 0; rr < 7; ++rr) {
        int row = ty * 7 + rr;
        float v[8]; float s = 0.f;
#pragma unroll
        for (int cc = 0; cc < 8; ++cc) {
            float2 f = unpk(accC2[rr][cc >> 1]);
            float raw = (cc & 1) ? f.y : f.x;
            int c = colmap(tx, cc);
            float t = 0.f;
            if (c < 250) t = fmaxf(raw + ctx_b[c], 0.f);
            v[cc] = t; s += t;
        }
        s = warp_sum(s);
        float mu = s * (1.f / 250.f);
        float q = 0.f;
#pragma unroll
        for (int cc = 0; cc < 8; ++cc) {
            int c = colmap(tx, cc);
            if (c < 250) { float d = v[cc] - mu; q += d * d; }
        }
        q = warp_sum(q);
        float rs = rsqrtf(q * (1.f / 250.f) + 1e-5f);
        float aw = sAtt[row];
#pragma unroll
        for (int cc = 0; cc < 8; ++cc) {
            int c = colmap(tx, cc);
            if (c < 250) eff[cc] += ((v[cc] - mu) * rs * ctx_g[c] + ctx_bt[c]) * aw;
        }
    }
#pragma unroll
    for (int cc = 0; cc < 8; ++cc) {
        int c = colmap(tx, cc);
        if (c < 250) effect[(size_t)(b * 8 + ty) * 250 + c] = eff[cc];
    }
}

// ---------------------------------------------------------------------------
extern "C" void kernel_launch(void* const* d_in, const int* in_sizes, int n_in,
                              void* d_out, int out_size)
{
    const float* x      = (const float*)d_in[0];
    const float* state  = (const float*)d_in[1];
    const float* enc_W  = (const float*)d_in[2];
    const float* enc_b  = (const float*)d_in[3];
    const float* enc_g  = (const float*)d_in[4];
    const float* enc_bt = (const float*)d_in[5];
    const float* core_W = (const float*)d_in[6];
    const float* core_b = (const float*)d_in[7];
    const float* core_g = (const float*)d_in[8];
    const float* core_bt= (const float*)d_in[9];
    const float* ctx_W  = (const float*)d_in[10];
    const float* ctx_b  = (const float*)d_in[11];
    const float* ctx_g  = (const float*)d_in[12];
    const float* ctx_bt = (const float*)d_in[13];
    const float* att_W1 = (const float*)d_in[14];
    const float* att_b1 = (const float*)d_in[15];
    const float* att_g  = (const float*)d_in[16];
    const float* att_bt = (const float*)d_in[17];
    const float* att_W2 = (const float*)d_in[18];
    const float* att_b2 = (const float*)d_in[19];
    const float* out_W  = (const float*)d_in[20];
    const float* out_b  = (const float*)d_in[21];
    float* out = (float*)d_out;

    float *p_s1, *p_P, *p_Q, *p_eff;
    cudaGetSymbolAddress((void**)&p_s1,  g_s1);
    cudaGetSymbolAddress((void**)&p_P,   g_P);
    cudaGetSymbolAddress((void**)&p_Q,   g_Q);
    cudaGetSymbolAddress((void**)&p_eff, g_eff);

    cudaFuncSetAttribute(pair_kernel, cudaFuncAttributeMaxDynamicSharedMemorySize,
                         SM_TOT * (int)sizeof(float));

    gemm_kernel<1><<<ROWS / 64, 256>>>(state, enc_W, enc_b, enc_g, enc_bt,
                                       p_s1, ROWS, 250, 250);
    gemm_kernel<0><<<ROWS / 64, 256>>>(p_s1, core_W, nullptr, nullptr, nullptr,
                                       p_P, ROWS, 250, 250);
    gemm_kernel<0><<<ROWS / 64, 256>>>(p_s1, core_W + 250 * 250, nullptr, nullptr, nullptr,
                                       p_Q, ROWS, 250, 250);
    pair_kernel<<<NB, 256, SM_TOT * (int)sizeof(float)>>>(
        p_P, p_Q, core_b, core_g, core_bt,
        ctx_W, ctx_b, ctx_g, ctx_bt,
        att_W1, att_b1, att_g, att_bt,
        att_W2, att_b2, p_eff);
    out_gemm_kernel<<<ROWS / 64, 256>>>(p_s1, p_eff, x, out_W, out_b, out);
}

// round 10
// speedup vs baseline: 1.1884x; 1.1884x over previous
#include <cuda_runtime.h>
#include <math.h>

#define NB     2048
#define KOBJ   8
#define H1     250
#define ROWS   (NB*KOBJ)       // 16384

__device__ float g_s1 [ROWS*H1];
__device__ float g_P  [ROWS*H1];
__device__ float g_Q  [ROWS*H1];
__device__ float g_eff[ROWS*H1];

typedef unsigned long long u64;

__device__ __forceinline__ float warp_sum(float v) {
#pragma unroll
    for (int o = 16; o; o >>= 1) v += __shfl_xor_sync(0xffffffffu, v, o);
    return v;
}
__device__ __forceinline__ void ffma2(u64& d, u64 a, u64 b) {
    asm("fma.rn.f32x2 %0, %1, %2, %0;" : "+l"(d) : "l"(a), "l"(b));
}
__device__ __forceinline__ u64 dup2(float x) {
    u64 r;
    asm("mov.b64 %0, {%1, %1};" : "=l"(r) : "r"(__float_as_uint(x)));
    return r;
}
__device__ __forceinline__ float2 unpk(u64 v) {
    float2 f;
    asm("mov.b64 {%0, %1}, %2;" : "=f"(f.x), "=f"(f.y) : "l"(v));
    return f;
}
__device__ __forceinline__ float fsel(float4 v, int m) {
    return (m == 0) ? v.x : (m == 1) ? v.y : (m == 2) ? v.z : v.w;
}
__device__ __forceinline__ void cp8(void* s, const void* g) {
    asm volatile("cp.async.ca.shared.global [%0], [%1], 8;"
                 :: "r"((unsigned)__cvta_generic_to_shared(s)), "l"(g));
}
__device__ __forceinline__ void cp4(void* s, const void* g) {
    asm volatile("cp.async.ca.shared.global [%0], [%1], 4;"
                 :: "r"((unsigned)__cvta_generic_to_shared(s)), "l"(g));
}
#define CP_COMMIT() asm volatile("cp.async.commit_group;")
#define CP_WAIT1()  asm volatile("cp.async.wait_group 1;")

__device__ __forceinline__ int colmap(int tx, int cc) {
    return (cc < 4) ? (tx * 4 + cc) : (128 + tx * 4 + (cc - 4));
}

// ---------------------------------------------------------------------------
// Tiled SGEMM (R7-best, unchanged): BM=64, BN=256, BK=16; 256 threads;
// cp.async double-buffered tiles; dup2 in loop; FFMA2 accumulators.
// ---------------------------------------------------------------------------
template <int EPI>
__global__ __launch_bounds__(256, 2)
void gemm_kernel(const float* __restrict__ A, const float* __restrict__ W,
                 const float* __restrict__ bias, const float* __restrict__ g,
                 const float* __restrict__ bt, float* __restrict__ C,
                 int M, int K, int N)
{
    __shared__ float sA[2][64 * 20];
    __shared__ float sW[2][16 * 256];
    const int tid = threadIdx.x;
    const int tx = tid & 31, ty = tid >> 5;
    const int row0 = blockIdx.x * 64;
    const int NT = (K + 15) >> 4;

    auto issue = [&](int t, int buf) {
        int kt = t * 16;
#pragma unroll
        for (int c = 0; c < 2; ++c) {
            int q = tid + c * 256;
            int r = q >> 3, kk0 = (q & 7) * 2;
            int k = kt + kk0;
            float* d = &sA[buf][r * 20 + kk0];
            if (k + 2 <= K)     cp8(d, &A[(size_t)(row0 + r) * K + k]);
            else if (k < K) { cp4(d, &A[(size_t)(row0 + r) * K + k]); d[1] = 0.f; }
            else *(float2*)d = make_float2(0.f, 0.f);
        }
#pragma unroll
        for (int c = 0; c < 8; ++c) {
            int q = tid + c * 256;
            int kk = q >> 7, n0 = (q & 127) * 2;
            int k = kt + kk;
            float* d = &sW[buf][kk * 256 + n0];
            if (k < K && n0 + 2 <= N)   cp8(d, &W[(size_t)k * N + n0]);
            else if (k < K && n0 < N) { cp4(d, &W[(size_t)k * N + n0]); d[1] = 0.f; }
            else *(float2*)d = make_float2(0.f, 0.f);
        }
    };

    u64 acc2[8][4];
#pragma unroll
    for (int r = 0; r < 8; ++r)
#pragma unroll
        for (int p = 0; p < 4; ++p) acc2[r][p] = 0ull;

    issue(0, 0); CP_COMMIT();
    for (int t = 0; t < NT; ++t) {
        if (t + 1 < NT) issue(t + 1, (t + 1) & 1);
        CP_COMMIT();
        CP_WAIT1();
        __syncthreads();
        const float* aT = sA[t & 1];
        const float* wT = sW[t & 1];
#pragma unroll
        for (int k4 = 0; k4 < 4; ++k4) {
            float4 a4[8];
#pragma unroll
            for (int rr = 0; rr < 8; ++rr)
                a4[rr] = *(const float4*)&aT[(ty * 8 + rr) * 20 + k4 * 4];
#pragma unroll
            for (int m = 0; m < 4; ++m) {
                int kk = k4 * 4 + m;
                ulonglong2 wv0 = *(const ulonglong2*)&wT[kk * 256 + tx * 4];
                ulonglong2 wv1 = *(const ulonglong2*)&wT[kk * 256 + 128 + tx * 4];
                u64 w2[4] = {wv0.x, wv0.y, wv1.x, wv1.y};
#pragma unroll
                for (int rr = 0; rr < 8; ++rr) {
                    u64 ad = dup2(fsel(a4[rr], m));
#pragma unroll
                    for (int p = 0; p < 4; ++p) ffma2(acc2[rr][p], ad, w2[p]);
                }
            }
        }
        __syncthreads();
    }

    if (EPI == 0) {
#pragma unroll
        for (int rr = 0; rr < 8; ++rr) {
            int row = row0 + ty * 8 + rr;
#pragma unroll
            for (int p = 0; p < 4; ++p) {
                float2 f = unpk(acc2[rr][p]);
                int n0 = colmap(tx, 2 * p);
                if (n0 < N)     C[(size_t)row * N + n0]     = f.x;
                if (n0 + 1 < N) C[(size_t)row * N + n0 + 1] = f.y;
            }
        }
    } else {
        float invN = 1.f / (float)N;
#pragma unroll
        for (int rr = 0; rr < 8; ++rr) {
            int row = row0 + ty * 8 + rr;
            float v[8]; float s = 0.f;
#pragma unroll
            for (int cc = 0; cc < 8; ++cc) {
                float2 f = unpk(acc2[rr][cc >> 1]);
                float raw = (cc & 1) ? f.y : f.x;
                int n = colmap(tx, cc);
                float t = 0.f;
                if (n < N) t = fmaxf(raw + bias[n], 0.f);
                v[cc] = t; s += t;
            }
            s = warp_sum(s);
            float mu = s * invN;
            float q = 0.f;
#pragma unroll
            for (int cc = 0; cc < 8; ++cc) {
                int n = colmap(tx, cc);
                if (n < N) { float d = v[cc] - mu; q += d * d; }
            }
            q = warp_sum(q);
            float rs = rsqrtf(q * invN + 1e-5f);
#pragma unroll
            for (int cc = 0; cc < 8; ++cc) {
                int n = colmap(tx, cc);
                if (n < N) C[(size_t)row * N + n] = (v[cc] - mu) * rs * g[n] + bt[n];
            }
        }
    }
}

// ---------------------------------------------------------------------------
// Output GEMM (R7-best, unchanged): [s1|effect|x] @ out_W + out_b.
// ---------------------------------------------------------------------------
__global__ __launch_bounds__(256, 2)
void out_gemm_kernel(const float* __restrict__ s1, const float* __restrict__ eff,
                     const float* __restrict__ x, const float* __restrict__ W,
                     const float* __restrict__ bias, float* __restrict__ C)
{
    const int K = 1076, N = 250;
    __shared__ float sA[2][64 * 20];
    __shared__ float sW[2][16 * 256];
    const int tid = threadIdx.x;
    const int tx = tid & 31, ty = tid >> 5;
    const int row0 = blockIdx.x * 64;
    const int NT = (K + 15) >> 4;   // 68

    auto issue = [&](int t, int buf) {
        int kt = t * 16;
#pragma unroll
        for (int c = 0; c < 4; ++c) {
            int q = tid + c * 256;
            int r = q >> 4, kk = q & 15;
            int k = kt + kk;
            int row = row0 + r;
            float* d = &sA[buf][r * 20 + kk];
            if (k < 250)       cp4(d, &s1 [(size_t)row * 250 + k]);
            else if (k < 500)  cp4(d, &eff[(size_t)row * 250 + (k - 250)]);
            else if (k < 1076) cp4(d, &x  [(size_t)row * 576 + (k - 500)]);
            else *d = 0.f;
        }
#pragma unroll
        for (int c = 0; c < 8; ++c) {
            int q = tid + c * 256;
            int kk = q >> 7, n0 = (q & 127) * 2;
            int k = kt + kk;
            float* d = &sW[buf][kk * 256 + n0];
            if (k < K && n0 + 2 <= N)   cp8(d, &W[(size_t)k * N + n0]);
            else if (k < K && n0 < N) { cp4(d, &W[(size_t)k * N + n0]); d[1] = 0.f; }
            else *(float2*)d = make_float2(0.f, 0.f);
        }
    };

    u64 acc2[8][4];
#pragma unroll
    for (int r = 0; r < 8; ++r)
#pragma unroll
        for (int p = 0; p < 4; ++p) acc2[r][p] = 0ull;

    issue(0, 0); CP_COMMIT();
    for (int t = 0; t < NT; ++t) {
        if (t + 1 < NT) issue(t + 1, (t + 1) & 1);
        CP_COMMIT();
        CP_WAIT1();
        __syncthreads();
        const float* aT = sA[t & 1];
        const float* wT = sW[t & 1];
#pragma unroll
        for (int k4 = 0; k4 < 4; ++k4) {
            float4 a4[8];
#pragma unroll
            for (int rr = 0; rr < 8; ++rr)
                a4[rr] = *(const float4*)&aT[(ty * 8 + rr) * 20 + k4 * 4];
#pragma unroll
            for (int m = 0; m < 4; ++m) {
                int kk = k4 * 4 + m;
                ulonglong2 wv0 = *(const ulonglong2*)&wT[kk * 256 + tx * 4];
                ulonglong2 wv1 = *(const ulonglong2*)&wT[kk * 256 + 128 + tx * 4];
                u64 w2[4] = {wv0.x, wv0.y, wv1.x, wv1.y};
#pragma unroll
                for (int rr = 0; rr < 8; ++rr) {
                    u64 ad = dup2(fsel(a4[rr], m));
#pragma unroll
                    for (int p = 0; p < 4; ++p) ffma2(acc2[rr][p], ad, w2[p]);
                }
            }
        }
        __syncthreads();
    }
#pragma unroll
    for (int rr = 0; rr < 8; ++rr) {
        int row = row0 + ty * 8 + rr;
#pragma unroll
        for (int p = 0; p < 4; ++p) {
            float2 f = unpk(acc2[rr][p]);
            int n0 = colmap(tx, 2 * p);
            if (n0 < N)     C[(size_t)row * N + n0]     = f.x + bias[n0];
            if (n0 + 1 < N) C[(size_t)row * N + n0 + 1] = f.y + bias[n0 + 1];
        }
    }
}

// ---------------------------------------------------------------------------
// Fused pair kernel v4: 512 threads, TWO b-groups per block (112 rows).
// Per-thread register demand identical to R7 (7 rows); W-tile loads are
// amortized over 2x compute and 2x threads; tiles double-buffered cp.async.
// Separate att then ctx phases (BK=32, 8 phases each).
// SMEM (floats): sC 112x256 = 28672 | ctx tiles 2x8192 | att tiles 2x4096
//   | sAtt 112 (+pad)  = 53376 floats = 213504 B  -> 1 block/SM, 16 warps.
// staging sP/sQ (8000 fl) overlaps ctx-tile region (phase-disjoint).
// ---------------------------------------------------------------------------
#define PSC    0
#define PUN    (112 * 256)              /* 28672 */
#define P_SATT (PUN + 24576)            /* 53248 */
#define P_TOT  (P_SATT + 128)           /* 53376 floats */

__global__ __launch_bounds__(512, 1)
void pair_kernel(const float* __restrict__ P, const float* __restrict__ Q,
                 const float* __restrict__ core_b, const float* __restrict__ core_g,
                 const float* __restrict__ core_bt,
                 const float* __restrict__ ctxW, const float* __restrict__ ctx_b,
                 const float* __restrict__ ctx_g, const float* __restrict__ ctx_bt,
                 const float* __restrict__ attW1, const float* __restrict__ att_b1,
                 const float* __restrict__ att_g, const float* __restrict__ att_bt,
                 const float* __restrict__ attW2, const float* __restrict__ att_b2,
                 float* __restrict__ effect)
{
    extern __shared__ float sm[];
    float* sC   = sm + PSC;             // 112 x 256 (cols 250..255 zero)
    float* sP   = sm + PUN;             // staging: 16 rows x 250, contiguous
    float* sQ   = sm + PUN + 4000;
    float* sAtt = sm + P_SATT;

    const int tid = threadIdx.x;
    const int tx = tid & 31, wy = tid >> 5;   // 16 warps
    const int b0 = blockIdx.x * 2;            // first of two b groups

    auto issue_att = [&](int t, int buf) {
        int kt0 = t * 32;
        float* dst = sm + PUN + 16384 + buf * 4096;   // 32 x 128
#pragma unroll
        for (int c = 0; c < 4; ++c) {
            int q = tid + c * 512;
            int kk = q >> 6, n = (q & 63) * 2;
            int k = kt0 + kk;
            float* d = &dst[kk * 128 + n];
            if (k < 250 && n + 2 <= 100) cp8(d, &attW1[(size_t)k * 100 + n]);
            else *(float2*)d = make_float2(0.f, 0.f);
        }
    };
    auto issue_ctx = [&](int t, int buf) {
        int kt0 = t * 32;
        float* dst = sm + PUN + buf * 8192;           // 32 x 256
#pragma unroll
        for (int c = 0; c < 8; ++c) {
            int q = tid + c * 512;
            int kk = q >> 7, n = (q & 127) * 2;
            int k = kt0 + kk;
            float* d = &dst[kk * 256 + n];
            if (k < 250 && n + 2 <= 250) cp8(d, &ctxW[(size_t)k * 250 + n]);
            else *(float2*)d = make_float2(0.f, 0.f);
        }
    };

    // prefetch first att tile immediately (att region disjoint from staging)
    issue_att(0, 0); CP_COMMIT();

    // --- phase 1: stage P,Q (16 contiguous rows each) + build core_out ---
#pragma unroll
    for (int c = 0; c < 2; ++c) {
        int idx = tid + c * 512;
        if (idx < 1000) {
            *(float4*)&sP[idx * 4] = *(const float4*)&P[(size_t)b0 * 2000 + idx * 4];
            *(float4*)&sQ[idx * 4] = *(const float4*)&Q[(size_t)b0 * 2000 + idx * 4];
        }
    }
    __syncthreads();

    for (int l = wy; l < 112; l += 16) {
        int bi = l / 56, pr = l % 56;
        int i = pr / 7, jj = pr % 7;
        int j = jj + (jj >= i ? 1 : 0);
        const float* Pr = &sP[(bi * 8 + i) * 250];
        const float* Qr = &sQ[(bi * 8 + j) * 250];
        float v[8]; float s = 0.f;
#pragma unroll
        for (int t = 0; t < 8; ++t) {
            int c = tx + 32 * t;
            float val = 0.f;
            if (c < 250) val = fmaxf(Pr[c] + Qr[c] + core_b[c], 0.f);
            v[t] = val; s += val;
        }
        s = warp_sum(s);
        float mu = s * (1.f / 250.f);
        float q = 0.f;
#pragma unroll
        for (int t = 0; t < 8; ++t) {
            int c = tx + 32 * t;
            if (c < 250) { float d = v[t] - mu; q += d * d; }
        }
        q = warp_sum(q);
        float rs = rsqrtf(q * (1.f / 250.f) + 1e-5f);
#pragma unroll
        for (int t = 0; t < 8; ++t) {
            int c = tx + 32 * t;
            if (c < 250) sC[l * 256 + c] = (v[t] - mu) * rs * core_g[c] + core_bt[c];
            else         sC[l * 256 + c] = 0.f;
        }
    }
    __syncthreads();   // staging dead; ctx tile region may be written later

    // --- phase 2: att GEMM 112 x 100, K=250, BK=32, double-buffered ---
    u64 accA2[7][2];
#pragma unroll
    for (int r = 0; r < 7; ++r) { accA2[r][0] = 0ull; accA2[r][1] = 0ull; }

    for (int t = 0; t < 8; ++t) {
        if (t < 7) issue_att(t + 1, (t + 1) & 1);
        CP_COMMIT();
        CP_WAIT1();
        __syncthreads();
        const float* wT = sm + PUN + 16384 + (t & 1) * 4096;
        int kt0 = t * 32;
#pragma unroll
        for (int k4 = 0; k4 < 8; ++k4) {
            float4 a4[7];
#pragma unroll
            for (int rr = 0; rr < 7; ++rr)
                a4[rr] = *(const float4*)&sC[(wy * 7 + rr) * 256 + kt0 + k4 * 4];
#pragma unroll
            for (int m = 0; m < 4; ++m) {
                int kk = k4 * 4 + m;
                ulonglong2 wa = *(const ulonglong2*)&wT[kk * 128 + tx * 4];
#pragma unroll
                for (int rr = 0; rr < 7; ++rr) {
                    u64 ad = dup2(fsel(a4[rr], m));
                    ffma2(accA2[rr][0], ad, wa.x);
                    ffma2(accA2[rr][1], ad, wa.y);
                }
            }
        }
        __syncthreads();
    }

    // prefetch ctx tile 0 before the epilogue register math
    issue_ctx(0, 0); CP_COMMIT();

    // --- attention epilogue: tanh, LN(100), dot attW2, sigmoid ---
#pragma unroll
    for (int rr = 0; rr < 7; ++rr) {
        int row = wy * 7 + rr;
        float h[4]; float s = 0.f;
#pragma unroll
        for (int cc = 0; cc < 4; ++cc) {
            float2 f = unpk(accA2[rr][cc >> 1]);
            float raw = (cc & 1) ? f.y : f.x;
            int c = tx * 4 + cc;
            float t = 0.f;
            if (c < 100) t = tanhf(raw + att_b1[c]);
            h[cc] = t; s += t;
        }
        s = warp_sum(s);
        float mu = s * (1.f / 100.f);
        float q = 0.f;
#pragma unroll
        for (int cc = 0; cc < 4; ++cc) {
            int c = tx * 4 + cc;
            if (c < 100) { float d = h[cc] - mu; q += d * d; }
        }
        q = warp_sum(q);
        float rs = rsqrtf(q * (1.f / 100.f) + 1e-5f);
        float p = 0.f;
#pragma unroll
        for (int cc = 0; cc < 4; ++cc) {
            int c = tx * 4 + cc;
            if (c < 100) p += ((h[cc] - mu) * rs * att_g[c] + att_bt[c]) * attW2[c];
        }
        p = warp_sum(p);
        if (tx == 0) sAtt[row] = 1.f / (1.f + expf(-(p + att_b2[0])));
    }
    __syncthreads();

    // --- phase 3: ctx GEMM 112 x 250, K=250, BK=32, double-buffered ---
    u64 accC2[7][4];
#pragma unroll
    for (int r = 0; r < 7; ++r)
#pragma unroll
        for (int p = 0; p < 4; ++p) accC2[r][p] = 0ull;

    for (int t = 0; t < 8; ++t) {
        if (t < 7) issue_ctx(t + 1, (t + 1) & 1);
        CP_COMMIT();
        CP_WAIT1();
        __syncthreads();
        const float* wT = sm + PUN + (t & 1) * 8192;
        int kt0 = t * 32;
#pragma unroll
        for (int k4 = 0; k4 < 8; ++k4) {
            float4 a4[7];
#pragma unroll
            for (int rr = 0; rr < 7; ++rr)
                a4[rr] = *(const float4*)&sC[(wy * 7 + rr) * 256 + kt0 + k4 * 4];
#pragma unroll
            for (int m = 0; m < 4; ++m) {
                int kk = k4 * 4 + m;
                ulonglong2 wv0 = *(const ulonglong2*)&wT[kk * 256 + tx * 4];
                ulonglong2 wv1 = *(const ulonglong2*)&wT[kk * 256 + 128 + tx * 4];
                u64 w2[4] = {wv0.x, wv0.y, wv1.x, wv1.y};
#pragma unroll
                for (int rr = 0; rr < 7; ++rr) {
                    u64 ad = dup2(fsel(a4[rr], m));
#pragma unroll
                    for (int p = 0; p < 4; ++p) ffma2(accC2[rr][p], ad, w2[p]);
                }
            }
        }
        __syncthreads();
    }

    // --- ctx epilogue + effect reduce (warp wy owns (bi=wy>>3, ig=wy&7)) ---
    const int bi = wy >> 3, ig = wy & 7;
    float eff[8];
#pragma unroll
    for (int cc = 0; cc < 8; ++cc) eff[cc] = 0.f;
#pragma unroll
    for (int rr = 0; rr < 7; ++rr) {
        int row = wy * 7 + rr;
        float v[8]; float s = 0.f;
#pragma unroll
        for (int cc = 0; cc < 8; ++cc) {
            float2 f = unpk(accC2[rr][cc >> 1]);
            float raw = (cc & 1) ? f.y : f.x;
            int c = colmap(tx, cc);
            float t = 0.f;
            if (c < 250) t = fmaxf(raw + ctx_b[c], 0.f);
            v[cc] = t; s += t;
        }
        s = warp_sum(s);
        float mu = s * (1.f / 250.f);
        float q = 0.f;
#pragma unroll
        for (int cc = 0; cc < 8; ++cc) {
            int c = colmap(tx, cc);
            if (c < 250) { float d = v[cc] - mu; q += d * d; }
        }
        q = warp_sum(q);
        float rs = rsqrtf(q * (1.f / 250.f) + 1e-5f);
        float aw = sAtt[row];
#pragma unroll
        for (int cc = 0; cc < 8; ++cc) {
            int c = colmap(tx, cc);
            if (c < 250) eff[cc] += ((v[cc] - mu) * rs * ctx_g[c] + ctx_bt[c]) * aw;
        }
    }
#pragma unroll
    for (int cc = 0; cc < 8; ++cc) {
        int c = colmap(tx, cc);
        if (c < 250) effect[((size_t)(b0 + bi) * 8 + ig) * 250 + c] = eff[cc];
    }
}

// ---------------------------------------------------------------------------
extern "C" void kernel_launch(void* const* d_in, const int* in_sizes, int n_in,
                              void* d_out, int out_size)
{
    const float* x      = (const float*)d_in[0];
    const float* state  = (const float*)d_in[1];
    const float* enc_W  = (const float*)d_in[2];
    const float* enc_b  = (const float*)d_in[3];
    const float* enc_g  = (const float*)d_in[4];
    const float* enc_bt = (const float*)d_in[5];
    const float* core_W = (const float*)d_in[6];
    const float* core_b = (const float*)d_in[7];
    const float* core_g = (const float*)d_in[8];
    const float* core_bt= (const float*)d_in[9];
    const float* ctx_W  = (const float*)d_in[10];
    const float* ctx_b  = (const float*)d_in[11];
    const float* ctx_g  = (const float*)d_in[12];
    const float* ctx_bt = (const float*)d_in[13];
    const float* att_W1 = (const float*)d_in[14];
    const float* att_b1 = (const float*)d_in[15];
    const float* att_g  = (const float*)d_in[16];
    const float* att_bt = (const float*)d_in[17];
    const float* att_W2 = (const float*)d_in[18];
    const float* att_b2 = (const float*)d_in[19];
    const float* out_W  = (const float*)d_in[20];
    const float* out_b  = (const float*)d_in[21];
    float* out = (float*)d_out;

    float *p_s1, *p_P, *p_Q, *p_eff;
    cudaGetSymbolAddress((void**)&p_s1,  g_s1);
    cudaGetSymbolAddress((void**)&p_P,   g_P);
    cudaGetSymbolAddress((void**)&p_Q,   g_Q);
    cudaGetSymbolAddress((void**)&p_eff, g_eff);

    cudaFuncSetAttribute(pair_kernel, cudaFuncAttributeMaxDynamicSharedMemorySize,
                         P_TOT * (int)sizeof(float));

    gemm_kernel<1><<<ROWS / 64, 256>>>(state, enc_W, enc_b, enc_g, enc_bt,
                                       p_s1, ROWS, 250, 250);
    gemm_kernel<0><<<ROWS / 64, 256>>>(p_s1, core_W, nullptr, nullptr, nullptr,
                                       p_P, ROWS, 250, 250);
    gemm_kernel<0><<<ROWS / 64, 256>>>(p_s1, core_W + 250 * 250, nullptr, nullptr, nullptr,
                                       p_Q, ROWS, 250, 250);
    pair_kernel<<<NB / 2, 512, P_TOT * (int)sizeof(float)>>>(
        p_P, p_Q, core_b, core_g, core_bt,
        ctx_W, ctx_b, ctx_g, ctx_bt,
        att_W1, att_b1, att_g, att_bt,
        att_W2, att_b2, p_eff);
    out_gemm_kernel<<<ROWS / 64, 256>>>(p_s1, p_eff, x, out_W, out_b, out);
}